// round 11
// baseline (speedup 1.0000x reference)
#include <cuda_runtime.h>
#include <cuda_fp16.h>

#define MAXN 100000
#define MAXE 1600000
#define HID 64
#define SCAN_BLK 1024
#define MAX_SCAN_BLOCKS 256

// ---- scratch (device globals; no allocation allowed) ----
__device__ __align__(256) __half g_t16[MAXN * HID];   // h @ W  (fp16 storage)
__device__ __align__(256) float g_agg[MAXN * HID];    // relu(conv) output (fp32)
__device__ __align__(256) float g_dis[MAXN];          // deg^{-1/2}
__device__ __align__(256) int   g_deg[MAXN];
__device__ __align__(256) int   g_rowptr[MAXN + 1];   // CSR row pointers (by dst)
__device__ __align__(256) int   g_cursor[MAXN];
__device__ __align__(256) int   g_blocksum[MAX_SCAN_BLOCKS];
__device__ __align__(256) int   g_blockoff[MAX_SCAN_BLOCKS];
__device__ __align__(256) int2  g_edge[MAXE + 4];     // CSR slot: (src, norm-bits); +4 pad stays 0

// ---------------- prep ----------------
__global__ void count_deg_kernel(const int* __restrict__ dst, int E) {
    int e = blockIdx.x * blockDim.x + threadIdx.x;
    if (e < E) atomicAdd(&g_deg[dst[e]], 1);
}

__global__ void scan_part_kernel(int n) {
    __shared__ int sm[256];
    int tid = threadIdx.x;
    int base = blockIdx.x * SCAN_BLK + tid * 4;
    int v[4];
#pragma unroll
    for (int j = 0; j < 4; j++) {
        v[j] = (base + j < n) ? g_deg[base + j] : 0;
        if (base + j < n) g_dis[base + j] = rsqrtf((float)(v[j] + 1));
    }
    int tsum = v[0] + v[1] + v[2] + v[3];
    sm[tid] = tsum;
    __syncthreads();
#pragma unroll
    for (int off = 1; off < 256; off <<= 1) {
        int t2 = (tid >= off) ? sm[tid - off] : 0;
        __syncthreads();
        sm[tid] += t2;
        __syncthreads();
    }
    if (tid == 255) g_blocksum[blockIdx.x] = sm[255];
    int run = sm[tid] - tsum;  // exclusive
#pragma unroll
    for (int j = 0; j < 4; j++) {
        if (base + j < n) g_rowptr[base + j] = run;
        run += v[j];
    }
}

__global__ void scan_top_kernel(int nb) {
    __shared__ int sm[256];
    int tid = threadIdx.x;
    int v = (tid < nb) ? g_blocksum[tid] : 0;
    sm[tid] = v;
    __syncthreads();
#pragma unroll
    for (int off = 1; off < 256; off <<= 1) {
        int t2 = (tid >= off) ? sm[tid - off] : 0;
        __syncthreads();
        sm[tid] += t2;
        __syncthreads();
    }
    if (tid < nb) g_blockoff[tid] = sm[tid] - v;  // exclusive
}

__global__ void scan_add_kernel(int n, int E) {
    int i = blockIdx.x * blockDim.x + threadIdx.x;
    if (i < n) {
        g_rowptr[i] += g_blockoff[i / SCAN_BLK];
        g_cursor[i] = 0;
    } else if (i == n) {
        g_rowptr[n] = E;
    }
}

__global__ void permute_kernel(const int* __restrict__ src,
                               const int* __restrict__ dst, int E) {
    int e = blockIdx.x * blockDim.x + threadIdx.x;
    if (e < E) {
        int s = src[e];
        int d = dst[e];
        int pos = atomicAdd(&g_cursor[d], 1);
        int slot = g_rowptr[d] + pos;
        g_edge[slot] = make_int2(s, __float_as_int(g_dis[s] * g_dis[d]));
    }
}

// ---------------- tf32 tensor-core GEMM: t16[N,64] = in[N,K] @ W[K,64] ----
__device__ __forceinline__ unsigned int f2tf32(float f) {
    unsigned int u;
    asm("cvt.rna.tf32.f32 %0, %1;" : "=r"(u) : "f"(f));
    return u;
}

__device__ __forceinline__ void mma_tf32(float* c,
                                         unsigned int a0, unsigned int a1,
                                         unsigned int a2, unsigned int a3,
                                         unsigned int b0, unsigned int b1) {
    asm volatile(
        "mma.sync.aligned.m16n8k8.row.col.f32.tf32.tf32.f32 "
        "{%0,%1,%2,%3}, {%4,%5,%6,%7}, {%8,%9}, {%0,%1,%2,%3};"
        : "+f"(c[0]), "+f"(c[1]), "+f"(c[2]), "+f"(c[3])
        : "r"(a0), "r"(a1), "r"(a2), "r"(a3), "r"(b0), "r"(b1));
}

// Block: 256 threads = 8 warps; tile = 128 nodes x 64 cols; warp = 16 nodes.
// A fragments loaded DIRECTLY from gmem (no smem staging, no tile sync).
// W in smem, stride 72 (== 8 mod 32: B-frag banks 8tg+g distinct, conflict-free).
template <int K>
__global__ __launch_bounds__(256) void gemm_tc_kernel(const float* __restrict__ in,
                                                      const float* __restrict__ W,
                                                      __half* __restrict__ out, int n) {
    constexpr int SW = 72;
    __shared__ unsigned int ws[K * SW];

    const int tid = threadIdx.x;
    const int base = blockIdx.x * 128;

    // load W -> smem (tf32)
    {
        const float4* W4 = (const float4*)W;
        for (int i = tid; i < K * 16; i += 256) {
            int row = i >> 4, c4 = i & 15;
            float4 v = W4[i];
            uint4 u = make_uint4(f2tf32(v.x), f2tf32(v.y), f2tf32(v.z), f2tf32(v.w));
            *(uint4*)(ws + row * SW + c4 * 4) = u;
        }
    }
    __syncthreads();

    const int wid  = tid >> 5;
    const int lane = tid & 31;
    const int g    = lane >> 2;   // group 0..7
    const int tg   = lane & 3;    // thread-in-group 0..3

    int r0 = base + wid * 16 + g;
    int r1 = r0 + 8;
    bool p0 = r0 < n, p1 = r1 < n;
    const float* x0 = in + (size_t)(p0 ? r0 : 0) * K + tg;
    const float* x1 = in + (size_t)(p1 ? r1 : 0) * K + tg;

    float c[8][4];
#pragma unroll
    for (int nt = 0; nt < 8; nt++)
#pragma unroll
        for (int j = 0; j < 4; j++) c[nt][j] = 0.f;

#pragma unroll
    for (int ks = 0; ks < K / 8; ks++) {
        float f0 = p0 ? x0[ks * 8]     : 0.f;
        float f2 = p0 ? x0[ks * 8 + 4] : 0.f;
        float f1 = p1 ? x1[ks * 8]     : 0.f;
        float f3 = p1 ? x1[ks * 8 + 4] : 0.f;
        unsigned int a0 = f2tf32(f0);
        unsigned int a2 = f2tf32(f2);
        unsigned int a1 = f2tf32(f1);
        unsigned int a3 = f2tf32(f3);
        const unsigned int* bp = ws + (ks * 8 + tg) * SW + g;
#pragma unroll
        for (int nt = 0; nt < 8; nt++) {
            unsigned int b0 = bp[nt * 8];
            unsigned int b1 = bp[nt * 8 + 4 * SW];
            mma_tf32(c[nt], a0, a1, a2, a3, b0, b1);
        }
    }

    // store fp16: lane holds rows (r0, r1), cols 8nt + 2tg, 2tg+1
#pragma unroll
    for (int nt = 0; nt < 8; nt++) {
        int col = nt * 8 + tg * 2;
        if (p0) {
            __half2 h = __floats2half2_rn(c[nt][0], c[nt][1]);
            *(__half2*)(out + (size_t)r0 * 64 + col) = h;
        }
        if (p1) {
            __half2 h = __floats2half2_rn(c[nt][2], c[nt][3]);
            *(__half2*)(out + (size_t)r1 * 64 + col) = h;
        }
    }
}

// ---------------- CSR gather (warp per node, fp16 rows, packed idx) --------
// agg[i] = relu( sum_e t[src_e]*norm_e + t[i]*dis_i^2 + b )
__global__ __launch_bounds__(256) void gather_kernel(const float* __restrict__ b,
                                                     int n) {
    int node = blockIdx.x * 8 + (threadIdx.x >> 5);  // 8 warps/block
    int l = threadIdx.x & 31;
    if (node >= n) return;

    int e  = g_rowptr[node];
    int e1 = g_rowptr[node + 1];

    const __half2* t2 = (const __half2*)g_t16;

    float2 acc = make_float2(0.f, 0.f);

    for (; e < e1; e += 4) {
        int2 p0 = g_edge[e];
        int2 p1 = g_edge[e + 1];
        int2 p2 = g_edge[e + 2];
        int2 p3 = g_edge[e + 3];
        float n0 = __int_as_float(p0.y);
        float n1 = (e + 1 < e1) ? __int_as_float(p1.y) : 0.f;
        float n2 = (e + 2 < e1) ? __int_as_float(p2.y) : 0.f;
        float n3 = (e + 3 < e1) ? __int_as_float(p3.y) : 0.f;
        float2 f0 = __half22float2(t2[p0.x * 32 + l]);
        float2 f1 = __half22float2(t2[p1.x * 32 + l]);
        float2 f2 = __half22float2(t2[p2.x * 32 + l]);
        float2 f3 = __half22float2(t2[p3.x * 32 + l]);
        acc.x = fmaf(f0.x, n0, acc.x); acc.y = fmaf(f0.y, n0, acc.y);
        acc.x = fmaf(f1.x, n1, acc.x); acc.y = fmaf(f1.y, n1, acc.y);
        acc.x = fmaf(f2.x, n2, acc.x); acc.y = fmaf(f2.y, n2, acc.y);
        acc.x = fmaf(f3.x, n3, acc.x); acc.y = fmaf(f3.y, n3, acc.y);
    }

    // self-loop + bias + relu
    float s = g_dis[node]; s = s * s;
    float2 v = __half22float2(t2[node * 32 + l]);
    float2 bb = ((const float2*)b)[l];
    acc.x = fmaxf(fmaf(v.x, s, acc.x) + bb.x, 0.f);
    acc.y = fmaxf(fmaf(v.y, s, acc.y) + bb.y, 0.f);

    ((float2*)g_agg)[node * 32 + l] = acc;
}

// ---------------- pooling + output linear ----------------
__global__ void pool_out_kernel(const int* __restrict__ batch,
                                const float* __restrict__ Wout,
                                const float* __restrict__ bout,
                                float* __restrict__ out,
                                float* __restrict__ pooled, int n) {
    int g = blockIdx.x;
    int c = threadIdx.x;  // 64 threads

    int a = 0, b = n;
    while (a < b) { int m = (a + b) >> 1; if (batch[m] < g) a = m + 1; else b = m; }
    int start = a;
    b = n;
    while (a < b) { int m = (a + b) >> 1; if (batch[m] <= g) a = m + 1; else b = m; }
    int end = a;

    float sum = 0.f, mx = 0.f;
#pragma unroll 4
    for (int i = start; i < end; i++) {
        float v = g_agg[(size_t)i * 64 + c];   // already relu'd
        sum += v;
        mx = fmaxf(mx, v);
    }
    int cnt = end - start;
    float mean = (cnt > 0) ? sum / (float)cnt : 0.f;

    pooled[(size_t)g * 128 + c] = mean;
    pooled[(size_t)g * 128 + 64 + c] = mx;

    float partial = mean * Wout[c] + mx * Wout[64 + c];
#pragma unroll
    for (int o = 16; o > 0; o >>= 1)
        partial += __shfl_down_sync(0xffffffffu, partial, o);
    __shared__ float ws[2];
    if ((threadIdx.x & 31) == 0) ws[threadIdx.x >> 5] = partial;
    __syncthreads();
    if (threadIdx.x == 0) out[g] = ws[0] + ws[1] + bout[0];
}

// ---------------- host ----------------
extern "C" void kernel_launch(void* const* d_in, const int* in_sizes, int n_in,
                              void* d_out, int out_size) {
    const float* x     = (const float*)d_in[0];
    const int*   edge  = (const int*)d_in[1];     // int64 inputs arrive as int32
    const int*   batch = (const int*)d_in[2];
    const float* W1 = (const float*)d_in[3];  const float* b1 = (const float*)d_in[4];
    const float* W2 = (const float*)d_in[5];  const float* b2 = (const float*)d_in[6];
    const float* W3 = (const float*)d_in[7];  const float* b3 = (const float*)d_in[8];
    const float* W4 = (const float*)d_in[9];  const float* b4 = (const float*)d_in[10];
    const float* Wout = (const float*)d_in[11]; const float* bout = (const float*)d_in[12];

    int N = in_sizes[0] / 128;
    int E = in_sizes[1] / 2;
    int G = out_size / 129;  // out[G,1] + pooled[G,128]

    const int* src = edge;
    const int* dst = edge + E;

    float* out_p    = (float*)d_out;
    float* pooled_p = out_p + G;

    __half* tptr = nullptr;
    float*  aptr = nullptr;
    int*    degptr = nullptr;
    cudaGetSymbolAddress((void**)&tptr, g_t16);
    cudaGetSymbolAddress((void**)&aptr, g_agg);
    cudaGetSymbolAddress((void**)&degptr, g_deg);

    // Static side stream + fork/join events (created once; host-side objects,
    // no device allocation). s2 is non-blocking so legacy-stream implicit
    // sync does not serialize the two graph branches.
    static cudaStream_t s2 = nullptr;
    static cudaEvent_t evFork = nullptr, evJoin = nullptr;
    if (s2 == nullptr) {
        cudaStreamCreateWithFlags(&s2, cudaStreamNonBlocking);
        cudaEventCreateWithFlags(&evFork, cudaEventDisableTiming);
        cudaEventCreateWithFlags(&evJoin, cudaEventDisableTiming);
    }

    int nsb      = (N + SCAN_BLK - 1) / SCAN_BLK;
    int gblocks  = (N + 127) / 128;
    int agblocks = (N + 7) / 8;

    // ---- branch A (side stream): degree + CSR build ----
    cudaEventRecord(evFork, 0);
    cudaStreamWaitEvent(s2, evFork, 0);
    cudaMemsetAsync(degptr, 0, N * sizeof(int), s2);
    count_deg_kernel<<<(E + 255) / 256, 256, 0, s2>>>(dst, E);
    scan_part_kernel<<<nsb, 256, 0, s2>>>(N);
    scan_top_kernel<<<1, 256, 0, s2>>>(nsb);
    scan_add_kernel<<<(N + 256) / 256, 256, 0, s2>>>(N, E);
    permute_kernel<<<(E + 255) / 256, 256, 0, s2>>>(src, dst, E);
    cudaEventRecord(evJoin, s2);

    // ---- branch B (main stream): layer-1 GEMM, overlaps CSR build ----
    gemm_tc_kernel<128><<<gblocks, 256>>>(x, W1, tptr, N);

    // join: gather needs both CSR and t16
    cudaStreamWaitEvent(0, evJoin, 0);

    gather_kernel<<<agblocks, 256>>>(b1, N);
    // layers 2..4 (inputs already relu'd by gather)
    gemm_tc_kernel<64><<<gblocks, 256>>>(aptr, W2, tptr, N);
    gather_kernel<<<agblocks, 256>>>(b2, N);

    gemm_tc_kernel<64><<<gblocks, 256>>>(aptr, W3, tptr, N);
    gather_kernel<<<agblocks, 256>>>(b3, N);

    gemm_tc_kernel<64><<<gblocks, 256>>>(aptr, W4, tptr, N);
    gather_kernel<<<agblocks, 256>>>(b4, N);

    // pooling (+ fused output linear)
    pool_out_kernel<<<G, 64>>>(batch, Wout, bout, out_p, pooled_p, N);
}

// round 13
// speedup vs baseline: 1.2989x; 1.2989x over previous
#include <cuda_runtime.h>
#include <cuda_fp16.h>

#define MAXN 100000
#define MAXE 1600000
#define HID 64
#define SCAN_BLK 1024
#define MAX_SCAN_BLOCKS 256

// ---- scratch (device globals; no allocation allowed) ----
// t' buffers: t'[i] = (h @ W)[i] * dis[i]  (fp16), ping-pong to avoid
// cross-block RAW races in the fused gather+gemm kernel.
__device__ __align__(256) __half g_t16a[MAXN * HID];
__device__ __align__(256) __half g_t16b[MAXN * HID];
__device__ __align__(256) float g_agg[MAXN * HID];    // final relu(conv) for pooling
__device__ __align__(256) float g_dis[MAXN];          // deg^{-1/2}
__device__ __align__(256) int   g_deg[MAXN];
__device__ __align__(256) int   g_rowptr[MAXN + 1];
__device__ __align__(256) int   g_cursor[MAXN];
__device__ __align__(256) int   g_blocksum[MAX_SCAN_BLOCKS];
__device__ __align__(256) int   g_blockoff[MAX_SCAN_BLOCKS];
__device__ __align__(256) int   g_srcs[MAXE + 4];     // CSR: src node per slot

// ---------------- prep ----------------
__global__ void count_deg_kernel(const int* __restrict__ dst, int E) {
    int e = blockIdx.x * blockDim.x + threadIdx.x;
    if (e < E) atomicAdd(&g_deg[dst[e]], 1);
}

__global__ void scan_part_kernel(int n) {
    __shared__ int sm[256];
    int tid = threadIdx.x;
    int base = blockIdx.x * SCAN_BLK + tid * 4;
    int v[4];
#pragma unroll
    for (int j = 0; j < 4; j++) {
        v[j] = (base + j < n) ? g_deg[base + j] : 0;
        if (base + j < n) g_dis[base + j] = rsqrtf((float)(v[j] + 1));
    }
    int tsum = v[0] + v[1] + v[2] + v[3];
    sm[tid] = tsum;
    __syncthreads();
#pragma unroll
    for (int off = 1; off < 256; off <<= 1) {
        int t2 = (tid >= off) ? sm[tid - off] : 0;
        __syncthreads();
        sm[tid] += t2;
        __syncthreads();
    }
    if (tid == 255) g_blocksum[blockIdx.x] = sm[255];
    int run = sm[tid] - tsum;  // exclusive
#pragma unroll
    for (int j = 0; j < 4; j++) {
        if (base + j < n) g_rowptr[base + j] = run;
        run += v[j];
    }
}

__global__ void scan_top_kernel(int nb) {
    __shared__ int sm[256];
    int tid = threadIdx.x;
    int v = (tid < nb) ? g_blocksum[tid] : 0;
    sm[tid] = v;
    __syncthreads();
#pragma unroll
    for (int off = 1; off < 256; off <<= 1) {
        int t2 = (tid >= off) ? sm[tid - off] : 0;
        __syncthreads();
        sm[tid] += t2;
        __syncthreads();
    }
    if (tid < nb) g_blockoff[tid] = sm[tid] - v;  // exclusive
}

__global__ void scan_add_kernel(int n, int E) {
    int i = blockIdx.x * blockDim.x + threadIdx.x;
    if (i < n) {
        g_rowptr[i] += g_blockoff[i / SCAN_BLK];
        g_cursor[i] = 0;
    } else if (i == n) {
        g_rowptr[n] = E;
    }
}

__global__ void permute_kernel(const int* __restrict__ src,
                               const int* __restrict__ dst, int E) {
    int e = blockIdx.x * blockDim.x + threadIdx.x;
    if (e < E) {
        int d = dst[e];
        int pos = atomicAdd(&g_cursor[d], 1);
        g_srcs[g_rowptr[d] + pos] = src[e];
    }
}

// ---------------- common MMA helpers ----------------
__device__ __forceinline__ unsigned int f2tf32(float f) {
    unsigned int u;
    asm("cvt.rna.tf32.f32 %0, %1;" : "=r"(u) : "f"(f));
    return u;
}

__device__ __forceinline__ void mma_tf32(float* c,
                                         unsigned int a0, unsigned int a1,
                                         unsigned int a2, unsigned int a3,
                                         unsigned int b0, unsigned int b1) {
    asm volatile(
        "mma.sync.aligned.m16n8k8.row.col.f32.tf32.tf32.f32 "
        "{%0,%1,%2,%3}, {%4,%5,%6,%7}, {%8,%9}, {%0,%1,%2,%3};"
        : "+f"(c[0]), "+f"(c[1]), "+f"(c[2]), "+f"(c[3])
        : "r"(a0), "r"(a1), "r"(a2), "r"(a3), "r"(b0), "r"(b1));
}

// warp-level edge accumulation for one node from tin: sum_e t'[src_e] + t'[node]
__device__ __forceinline__ float2 gather_node(const __half2* __restrict__ t2,
                                              int node, int l) {
    float2 acc = __half22float2(t2[node * 32 + l]);  // self-loop term t'[d]
    int e  = g_rowptr[node];
    int e1 = g_rowptr[node + 1];
    for (; e + 4 <= e1; e += 4) {
        int s0 = g_srcs[e];
        int s1 = g_srcs[e + 1];
        int s2 = g_srcs[e + 2];
        int s3 = g_srcs[e + 3];
        float2 f0 = __half22float2(t2[s0 * 32 + l]);
        float2 f1 = __half22float2(t2[s1 * 32 + l]);
        float2 f2 = __half22float2(t2[s2 * 32 + l]);
        float2 f3 = __half22float2(t2[s3 * 32 + l]);
        acc.x += f0.x + f1.x + f2.x + f3.x;
        acc.y += f0.y + f1.y + f2.y + f3.y;
    }
    for (; e < e1; e++) {
        float2 f0 = __half22float2(t2[g_srcs[e] * 32 + l]);
        acc.x += f0.x;
        acc.y += f0.y;
    }
    return acc;
}

// ---------------- gemm1: tout[N,64] = (x[N,128] @ W1) * dis ----------------
__global__ __launch_bounds__(256) void gemm1_kernel(const float* __restrict__ in,
                                                    const float* __restrict__ W,
                                                    __half* __restrict__ out, int n) {
    constexpr int K = 128, SW = 72;
    __shared__ unsigned int ws[K * SW];

    const int tid = threadIdx.x;
    const int base = blockIdx.x * 128;

    {
        const float4* W4 = (const float4*)W;
        for (int i = tid; i < K * 16; i += 256) {
            int row = i >> 4, c4 = i & 15;
            float4 v = W4[i];
            uint4 u = make_uint4(f2tf32(v.x), f2tf32(v.y), f2tf32(v.z), f2tf32(v.w));
            *(uint4*)(ws + row * SW + c4 * 4) = u;
        }
    }
    __syncthreads();

    const int wid  = tid >> 5;
    const int lane = tid & 31;
    const int g    = lane >> 2;
    const int tg   = lane & 3;

    int r0 = base + wid * 16 + g;
    int r1 = r0 + 8;
    bool p0 = r0 < n, p1 = r1 < n;
    const float* x0 = in + (size_t)(p0 ? r0 : 0) * K + tg;
    const float* x1 = in + (size_t)(p1 ? r1 : 0) * K + tg;

    float c[8][4];
#pragma unroll
    for (int nt = 0; nt < 8; nt++)
#pragma unroll
        for (int j = 0; j < 4; j++) c[nt][j] = 0.f;

#pragma unroll
    for (int ks = 0; ks < K / 8; ks++) {
        unsigned int a0 = f2tf32(p0 ? x0[ks * 8]     : 0.f);
        unsigned int a2 = f2tf32(p0 ? x0[ks * 8 + 4] : 0.f);
        unsigned int a1 = f2tf32(p1 ? x1[ks * 8]     : 0.f);
        unsigned int a3 = f2tf32(p1 ? x1[ks * 8 + 4] : 0.f);
        const unsigned int* bp = ws + (ks * 8 + tg) * SW + g;
#pragma unroll
        for (int nt = 0; nt < 8; nt++) {
            unsigned int b0 = bp[nt * 8];
            unsigned int b1 = bp[nt * 8 + 4 * SW];
            mma_tf32(c[nt], a0, a1, a2, a3, b0, b1);
        }
    }

    float d0 = p0 ? g_dis[r0] : 0.f;
    float d1 = p1 ? g_dis[r1] : 0.f;
#pragma unroll
    for (int nt = 0; nt < 8; nt++) {
        int col = nt * 8 + tg * 2;
        if (p0) {
            __half2 h = __floats2half2_rn(c[nt][0] * d0, c[nt][1] * d0);
            *(__half2*)(out + (size_t)r0 * 64 + col) = h;
        }
        if (p1) {
            __half2 h = __floats2half2_rn(c[nt][2] * d1, c[nt][3] * d1);
            *(__half2*)(out + (size_t)r1 * 64 + col) = h;
        }
    }
}

// ---------------- fused: gather(tin) -> relu/bias -> gemm W -> tout ---------
// agg[d] = relu(dis[d]*(sum + self) + b_prev);  tout = (agg @ W) * dis
// tin != tout (ping-pong) -> no cross-block hazard.
__global__ __launch_bounds__(256) void fused_kernel(const __half2* __restrict__ tin,
                                                    __half* __restrict__ tout,
                                                    const float* __restrict__ b_prev,
                                                    const float* __restrict__ W,
                                                    int n) {
    constexpr int K = 64, SA = 68, SW = 72;
    extern __shared__ unsigned int smu[];
    unsigned int* xs = smu;             // 128 * SA
    unsigned int* ws = smu + 128 * SA;  // K * SW

    const int tid  = threadIdx.x;
    const int base = blockIdx.x * 128;
    const int wid  = tid >> 5;
    const int lane = tid & 31;

    // load W -> smem (tf32)
    {
        const float4* W4 = (const float4*)W;
        for (int i = tid; i < K * 16; i += 256) {
            int row = i >> 4, c4 = i & 15;
            float4 v = W4[i];
            uint4 u = make_uint4(f2tf32(v.x), f2tf32(v.y), f2tf32(v.z), f2tf32(v.w));
            *(uint4*)(ws + row * SW + c4 * 4) = u;
        }
    }

    // phase A: gather 16 nodes per warp into xs (tf32 agg rows)
    {
        float2 bb = ((const float2*)b_prev)[lane];
        for (int i = 0; i < 16; i++) {
            int nl = wid * 16 + i;
            int node = base + nl;
            unsigned int u0 = 0, u1 = 0;
            if (node < n) {
                float2 acc = gather_node(tin, node, lane);
                float dd = g_dis[node];
                u0 = f2tf32(fmaxf(fmaf(dd, acc.x, bb.x), 0.f));
                u1 = f2tf32(fmaxf(fmaf(dd, acc.y, bb.y), 0.f));
            }
            *(uint2*)(xs + nl * SA + lane * 2) = make_uint2(u0, u1);
        }
    }
    __syncthreads();

    // phase B: MMA from smem
    const int g  = lane >> 2;
    const int tg = lane & 3;

    float c[8][4];
#pragma unroll
    for (int nt = 0; nt < 8; nt++)
#pragma unroll
        for (int j = 0; j < 4; j++) c[nt][j] = 0.f;

    const unsigned int* arow0 = xs + (wid * 16 + g) * SA + tg;
    const unsigned int* arow1 = arow0 + 8 * SA;

#pragma unroll
    for (int ks = 0; ks < K / 8; ks++) {
        unsigned int a0 = arow0[ks * 8];
        unsigned int a2 = arow0[ks * 8 + 4];
        unsigned int a1 = arow1[ks * 8];
        unsigned int a3 = arow1[ks * 8 + 4];
        const unsigned int* bp = ws + (ks * 8 + tg) * SW + g;
#pragma unroll
        for (int nt = 0; nt < 8; nt++) {
            unsigned int b0 = bp[nt * 8];
            unsigned int b1 = bp[nt * 8 + 4 * SW];
            mma_tf32(c[nt], a0, a1, a2, a3, b0, b1);
        }
    }

    int r0 = base + wid * 16 + g;
    int r1 = r0 + 8;
    bool p0 = r0 < n, p1 = r1 < n;
    float d0 = p0 ? g_dis[r0] : 0.f;
    float d1 = p1 ? g_dis[r1] : 0.f;
#pragma unroll
    for (int nt = 0; nt < 8; nt++) {
        int col = nt * 8 + tg * 2;
        if (p0) {
            __half2 h = __floats2half2_rn(c[nt][0] * d0, c[nt][1] * d0);
            *(__half2*)(tout + (size_t)r0 * 64 + col) = h;
        }
        if (p1) {
            __half2 h = __floats2half2_rn(c[nt][2] * d1, c[nt][3] * d1);
            *(__half2*)(tout + (size_t)r1 * 64 + col) = h;
        }
    }
}

// ---------------- final gather: g_agg = relu(dis*(sum+self) + b4) ----------
__global__ __launch_bounds__(256) void gather_final_kernel(const __half2* __restrict__ tin,
                                                           const float* __restrict__ b,
                                                           int n) {
    int node = blockIdx.x * 8 + (threadIdx.x >> 5);
    int l = threadIdx.x & 31;
    if (node >= n) return;

    float2 acc = gather_node(tin, node, l);
    float dd = g_dis[node];
    float2 bb = ((const float2*)b)[l];
    float2 r;
    r.x = fmaxf(fmaf(dd, acc.x, bb.x), 0.f);
    r.y = fmaxf(fmaf(dd, acc.y, bb.y), 0.f);
    ((float2*)g_agg)[node * 32 + l] = r;
}

// ---------------- pooling + output linear ----------------
__global__ void pool_out_kernel(const int* __restrict__ batch,
                                const float* __restrict__ Wout,
                                const float* __restrict__ bout,
                                float* __restrict__ out,
                                float* __restrict__ pooled, int n) {
    int g = blockIdx.x;
    int c = threadIdx.x;  // 64 threads

    int a = 0, b = n;
    while (a < b) { int m = (a + b) >> 1; if (batch[m] < g) a = m + 1; else b = m; }
    int start = a;
    b = n;
    while (a < b) { int m = (a + b) >> 1; if (batch[m] <= g) a = m + 1; else b = m; }
    int end = a;

    float sum = 0.f, mx = 0.f;
#pragma unroll 4
    for (int i = start; i < end; i++) {
        float v = g_agg[(size_t)i * 64 + c];   // already relu'd
        sum += v;
        mx = fmaxf(mx, v);
    }
    int cnt = end - start;
    float mean = (cnt > 0) ? sum / (float)cnt : 0.f;

    pooled[(size_t)g * 128 + c] = mean;
    pooled[(size_t)g * 128 + 64 + c] = mx;

    float partial = mean * Wout[c] + mx * Wout[64 + c];
#pragma unroll
    for (int o = 16; o > 0; o >>= 1)
        partial += __shfl_down_sync(0xffffffffu, partial, o);
    __shared__ float ws[2];
    if ((threadIdx.x & 31) == 0) ws[threadIdx.x >> 5] = partial;
    __syncthreads();
    if (threadIdx.x == 0) out[g] = ws[0] + ws[1] + bout[0];
}

// ---------------- host ----------------
extern "C" void kernel_launch(void* const* d_in, const int* in_sizes, int n_in,
                              void* d_out, int out_size) {
    const float* x     = (const float*)d_in[0];
    const int*   edge  = (const int*)d_in[1];     // int64 inputs arrive as int32
    const int*   batch = (const int*)d_in[2];
    const float* W1 = (const float*)d_in[3];  const float* b1 = (const float*)d_in[4];
    const float* W2 = (const float*)d_in[5];  const float* b2 = (const float*)d_in[6];
    const float* W3 = (const float*)d_in[7];  const float* b3 = (const float*)d_in[8];
    const float* W4 = (const float*)d_in[9];  const float* b4 = (const float*)d_in[10];
    const float* Wout = (const float*)d_in[11]; const float* bout = (const float*)d_in[12];

    int N = in_sizes[0] / 128;
    int E = in_sizes[1] / 2;
    int G = out_size / 129;  // out[G,1] + pooled[G,128]

    const int* src = edge;
    const int* dst = edge + E;

    float* out_p    = (float*)d_out;
    float* pooled_p = out_p + G;

    int* degptr = nullptr;
    __half *ta = nullptr, *tb = nullptr;
    cudaGetSymbolAddress((void**)&degptr, g_deg);
    cudaGetSymbolAddress((void**)&ta, g_t16a);
    cudaGetSymbolAddress((void**)&tb, g_t16b);

    const int smemF = (128 * 68 + 64 * 72) * (int)sizeof(unsigned int);  // 53248B
    cudaFuncSetAttribute(fused_kernel,
                         cudaFuncAttributeMaxDynamicSharedMemorySize, smemF);

    int nsb      = (N + SCAN_BLK - 1) / SCAN_BLK;
    int gblocks  = (N + 127) / 128;
    int agblocks = (N + 7) / 8;

    // ---- prep + layer 1 (single stream) ----
    cudaMemsetAsync(degptr, 0, N * sizeof(int));
    count_deg_kernel<<<(E + 255) / 256, 256>>>(dst, E);
    scan_part_kernel<<<nsb, 256>>>(N);              // computes g_dis
    gemm1_kernel<<<gblocks, 256>>>(x, W1, ta, N);   // profiled slot 3 (needs dis only)
    scan_top_kernel<<<1, 256>>>(nsb);
    scan_add_kernel<<<(N + 256) / 256, 256>>>(N, E);
    permute_kernel<<<(E + 255) / 256, 256>>>(src, dst, E);

    // layers 2..4: fused gather(prev) + gemm(next), ping-pong a<->b
    fused_kernel<<<gblocks, 256, smemF>>>((const __half2*)ta, tb, b1, W2, N);
    fused_kernel<<<gblocks, 256, smemF>>>((const __half2*)tb, ta, b2, W3, N);
    fused_kernel<<<gblocks, 256, smemF>>>((const __half2*)ta, tb, b3, W4, N);

    // final gather -> g_agg (relu), then pooling + output linear
    gather_final_kernel<<<agblocks, 256>>>((const __half2*)tb, b4, N);
    pool_out_kernel<<<G, 64>>>(batch, Wout, bout, out_p, pooled_p, N);
}

// round 14
// speedup vs baseline: 1.6125x; 1.2414x over previous
#include <cuda_runtime.h>
#include <cuda_fp16.h>

#define MAXN 100000
#define MAXE 1600000
#define HID 64
#define SCAN_BLK 1024
#define MAX_SCAN_BLOCKS 256

// ---- scratch (device globals; no allocation allowed) ----
// g_t16 holds t'[i] = (h @ W)[i] * dis[i]  (fp16)
__device__ __align__(256) __half g_t16[MAXN * HID];
__device__ __align__(256) float g_agg[MAXN * HID];    // relu(conv) output (fp32)
__device__ __align__(256) float g_dis[MAXN];          // deg^{-1/2}
__device__ __align__(256) int   g_deg[MAXN];
__device__ __align__(256) int   g_rowptr[MAXN + 1];
__device__ __align__(256) int   g_cursor[MAXN];
__device__ __align__(256) int   g_blocksum[MAX_SCAN_BLOCKS];
__device__ __align__(256) int   g_blockoff[MAX_SCAN_BLOCKS];
__device__ __align__(256) int   g_srcs[MAXE + 4];     // CSR: src node per slot (+pad stays 0)

// ---------------- prep ----------------
__global__ void count_deg_kernel(const int* __restrict__ dst, int E) {
    int e = blockIdx.x * blockDim.x + threadIdx.x;
    if (e < E) atomicAdd(&g_deg[dst[e]], 1);
}

__global__ void scan_part_kernel(int n) {
    __shared__ int sm[256];
    int tid = threadIdx.x;
    int base = blockIdx.x * SCAN_BLK + tid * 4;
    int v[4];
#pragma unroll
    for (int j = 0; j < 4; j++) {
        v[j] = (base + j < n) ? g_deg[base + j] : 0;
        if (base + j < n) g_dis[base + j] = rsqrtf((float)(v[j] + 1));
    }
    int tsum = v[0] + v[1] + v[2] + v[3];
    sm[tid] = tsum;
    __syncthreads();
#pragma unroll
    for (int off = 1; off < 256; off <<= 1) {
        int t2 = (tid >= off) ? sm[tid - off] : 0;
        __syncthreads();
        sm[tid] += t2;
        __syncthreads();
    }
    if (tid == 255) g_blocksum[blockIdx.x] = sm[255];
    int run = sm[tid] - tsum;  // exclusive
#pragma unroll
    for (int j = 0; j < 4; j++) {
        if (base + j < n) g_rowptr[base + j] = run;
        run += v[j];
    }
}

__global__ void scan_top_kernel(int nb) {
    __shared__ int sm[256];
    int tid = threadIdx.x;
    int v = (tid < nb) ? g_blocksum[tid] : 0;
    sm[tid] = v;
    __syncthreads();
#pragma unroll
    for (int off = 1; off < 256; off <<= 1) {
        int t2 = (tid >= off) ? sm[tid - off] : 0;
        __syncthreads();
        sm[tid] += t2;
        __syncthreads();
    }
    if (tid < nb) g_blockoff[tid] = sm[tid] - v;  // exclusive
}

__global__ void scan_add_kernel(int n, int E) {
    int i = blockIdx.x * blockDim.x + threadIdx.x;
    if (i < n) {
        g_rowptr[i] += g_blockoff[i / SCAN_BLK];
        g_cursor[i] = 0;
    } else if (i == n) {
        g_rowptr[n] = E;
    }
}

__global__ void permute_kernel(const int* __restrict__ src,
                               const int* __restrict__ dst, int E) {
    int e = blockIdx.x * blockDim.x + threadIdx.x;
    if (e < E) {
        int d = dst[e];
        int pos = atomicAdd(&g_cursor[d], 1);
        g_srcs[g_rowptr[d] + pos] = src[e];
    }
}

// ---------------- tf32 tensor-core GEMM: t16[N,64] = (in[N,K] @ W) * dis ----
__device__ __forceinline__ unsigned int f2tf32(float f) {
    unsigned int u;
    asm("cvt.rna.tf32.f32 %0, %1;" : "=r"(u) : "f"(f));
    return u;
}

__device__ __forceinline__ void mma_tf32(float* c,
                                         unsigned int a0, unsigned int a1,
                                         unsigned int a2, unsigned int a3,
                                         unsigned int b0, unsigned int b1) {
    asm volatile(
        "mma.sync.aligned.m16n8k8.row.col.f32.tf32.tf32.f32 "
        "{%0,%1,%2,%3}, {%4,%5,%6,%7}, {%8,%9}, {%0,%1,%2,%3};"
        : "+f"(c[0]), "+f"(c[1]), "+f"(c[2]), "+f"(c[3])
        : "r"(a0), "r"(a1), "r"(a2), "r"(a3), "r"(b0), "r"(b1));
}

// Block: 256 threads = 8 warps; tile = 128 nodes x 64 cols; warp = 16 nodes.
// A fragments loaded DIRECTLY from gmem (no smem staging, no tile sync).
// W in smem, stride 72 (== 8 mod 32: B-frag banks conflict-free).
// Epilogue: scale row r by dis[r] before fp16 store (norm factorization).
template <int K>
__global__ __launch_bounds__(256) void gemm_tc_kernel(const float* __restrict__ in,
                                                      const float* __restrict__ W,
                                                      __half* __restrict__ out, int n) {
    constexpr int SW = 72;
    __shared__ unsigned int ws[K * SW];

    const int tid = threadIdx.x;
    const int base = blockIdx.x * 128;

    {
        const float4* W4 = (const float4*)W;
        for (int i = tid; i < K * 16; i += 256) {
            int row = i >> 4, c4 = i & 15;
            float4 v = W4[i];
            uint4 u = make_uint4(f2tf32(v.x), f2tf32(v.y), f2tf32(v.z), f2tf32(v.w));
            *(uint4*)(ws + row * SW + c4 * 4) = u;
        }
    }
    __syncthreads();

    const int wid  = tid >> 5;
    const int lane = tid & 31;
    const int g    = lane >> 2;
    const int tg   = lane & 3;

    int r0 = base + wid * 16 + g;
    int r1 = r0 + 8;
    bool p0 = r0 < n, p1 = r1 < n;
    const float* x0 = in + (size_t)(p0 ? r0 : 0) * K + tg;
    const float* x1 = in + (size_t)(p1 ? r1 : 0) * K + tg;

    float c[8][4];
#pragma unroll
    for (int nt = 0; nt < 8; nt++)
#pragma unroll
        for (int j = 0; j < 4; j++) c[nt][j] = 0.f;

#pragma unroll
    for (int ks = 0; ks < K / 8; ks++) {
        unsigned int a0 = f2tf32(p0 ? x0[ks * 8]     : 0.f);
        unsigned int a2 = f2tf32(p0 ? x0[ks * 8 + 4] : 0.f);
        unsigned int a1 = f2tf32(p1 ? x1[ks * 8]     : 0.f);
        unsigned int a3 = f2tf32(p1 ? x1[ks * 8 + 4] : 0.f);
        const unsigned int* bp = ws + (ks * 8 + tg) * SW + g;
#pragma unroll
        for (int nt = 0; nt < 8; nt++) {
            unsigned int b0 = bp[nt * 8];
            unsigned int b1 = bp[nt * 8 + 4 * SW];
            mma_tf32(c[nt], a0, a1, a2, a3, b0, b1);
        }
    }

    float d0 = p0 ? g_dis[r0] : 0.f;
    float d1 = p1 ? g_dis[r1] : 0.f;
#pragma unroll
    for (int nt = 0; nt < 8; nt++) {
        int col = nt * 8 + tg * 2;
        if (p0) {
            __half2 h = __floats2half2_rn(c[nt][0] * d0, c[nt][1] * d0);
            *(__half2*)(out + (size_t)r0 * 64 + col) = h;
        }
        if (p1) {
            __half2 h = __floats2half2_rn(c[nt][2] * d1, c[nt][3] * d1);
            *(__half2*)(out + (size_t)r1 * 64 + col) = h;
        }
    }
}

// ---------------- CSR gather (warp per node, 4B edges, no weights) ---------
// agg[d] = relu( dis[d] * (sum_e t'[src_e] + t'[d]) + b )
__global__ __launch_bounds__(256) void gather_kernel(const float* __restrict__ b,
                                                     int n) {
    int node = blockIdx.x * 8 + (threadIdx.x >> 5);  // 8 warps/block
    int l = threadIdx.x & 31;
    if (node >= n) return;

    const __half2* t2 = (const __half2*)g_t16;

    float2 acc = __half22float2(t2[node * 32 + l]);  // self-loop term t'[d]
    int e  = g_rowptr[node];
    int e1 = g_rowptr[node + 1];
    for (; e + 4 <= e1; e += 4) {
        int s0 = g_srcs[e];
        int s1 = g_srcs[e + 1];
        int s2 = g_srcs[e + 2];
        int s3 = g_srcs[e + 3];
        float2 f0 = __half22float2(t2[s0 * 32 + l]);
        float2 f1 = __half22float2(t2[s1 * 32 + l]);
        float2 f2 = __half22float2(t2[s2 * 32 + l]);
        float2 f3 = __half22float2(t2[s3 * 32 + l]);
        acc.x += f0.x + f1.x + f2.x + f3.x;
        acc.y += f0.y + f1.y + f2.y + f3.y;
    }
    for (; e < e1; e++) {
        float2 f0 = __half22float2(t2[g_srcs[e] * 32 + l]);
        acc.x += f0.x;
        acc.y += f0.y;
    }

    float dd = g_dis[node];
    float2 bb = ((const float2*)b)[l];
    float2 r;
    r.x = fmaxf(fmaf(dd, acc.x, bb.x), 0.f);
    r.y = fmaxf(fmaf(dd, acc.y, bb.y), 0.f);
    ((float2*)g_agg)[node * 32 + l] = r;
}

// ---------------- pooling + output linear ----------------
__global__ void pool_out_kernel(const int* __restrict__ batch,
                                const float* __restrict__ Wout,
                                const float* __restrict__ bout,
                                float* __restrict__ out,
                                float* __restrict__ pooled, int n) {
    int g = blockIdx.x;
    int c = threadIdx.x;  // 64 threads

    int a = 0, b = n;
    while (a < b) { int m = (a + b) >> 1; if (batch[m] < g) a = m + 1; else b = m; }
    int start = a;
    b = n;
    while (a < b) { int m = (a + b) >> 1; if (batch[m] <= g) a = m + 1; else b = m; }
    int end = a;

    float sum = 0.f, mx = 0.f;
#pragma unroll 4
    for (int i = start; i < end; i++) {
        float v = g_agg[(size_t)i * 64 + c];   // already relu'd
        sum += v;
        mx = fmaxf(mx, v);
    }
    int cnt = end - start;
    float mean = (cnt > 0) ? sum / (float)cnt : 0.f;

    pooled[(size_t)g * 128 + c] = mean;
    pooled[(size_t)g * 128 + 64 + c] = mx;

    float partial = mean * Wout[c] + mx * Wout[64 + c];
#pragma unroll
    for (int o = 16; o > 0; o >>= 1)
        partial += __shfl_down_sync(0xffffffffu, partial, o);
    __shared__ float ws[2];
    if ((threadIdx.x & 31) == 0) ws[threadIdx.x >> 5] = partial;
    __syncthreads();
    if (threadIdx.x == 0) out[g] = ws[0] + ws[1] + bout[0];
}

// ---------------- host ----------------
extern "C" void kernel_launch(void* const* d_in, const int* in_sizes, int n_in,
                              void* d_out, int out_size) {
    const float* x     = (const float*)d_in[0];
    const int*   edge  = (const int*)d_in[1];     // int64 inputs arrive as int32
    const int*   batch = (const int*)d_in[2];
    const float* W1 = (const float*)d_in[3];  const float* b1 = (const float*)d_in[4];
    const float* W2 = (const float*)d_in[5];  const float* b2 = (const float*)d_in[6];
    const float* W3 = (const float*)d_in[7];  const float* b3 = (const float*)d_in[8];
    const float* W4 = (const float*)d_in[9];  const float* b4 = (const float*)d_in[10];
    const float* Wout = (const float*)d_in[11]; const float* bout = (const float*)d_in[12];

    int N = in_sizes[0] / 128;
    int E = in_sizes[1] / 2;
    int G = out_size / 129;  // out[G,1] + pooled[G,128]

    const int* src = edge;
    const int* dst = edge + E;

    float* out_p    = (float*)d_out;
    float* pooled_p = out_p + G;

    __half* tptr = nullptr;
    float*  aptr = nullptr;
    int*    degptr = nullptr;
    cudaGetSymbolAddress((void**)&tptr, g_t16);
    cudaGetSymbolAddress((void**)&aptr, g_agg);
    cudaGetSymbolAddress((void**)&degptr, g_deg);

    int nsb      = (N + SCAN_BLK - 1) / SCAN_BLK;
    int gblocks  = (N + 127) / 128;
    int agblocks = (N + 7) / 8;

    // ---- prep + layer 1 (single stream) ----
    cudaMemsetAsync(degptr, 0, N * sizeof(int));
    count_deg_kernel<<<(E + 255) / 256, 256>>>(dst, E);
    scan_part_kernel<<<nsb, 256>>>(N);                 // computes g_dis
    gemm_tc_kernel<128><<<gblocks, 256>>>(x, W1, tptr, N);  // profiled slot 3
    scan_top_kernel<<<1, 256>>>(nsb);
    scan_add_kernel<<<(N + 256) / 256, 256>>>(N, E);
    permute_kernel<<<(E + 255) / 256, 256>>>(src, dst, E);

    gather_kernel<<<agblocks, 256>>>(b1, N);
    // layers 2..4
    gemm_tc_kernel<64><<<gblocks, 256>>>(aptr, W2, tptr, N);
    gather_kernel<<<agblocks, 256>>>(b2, N);

    gemm_tc_kernel<64><<<gblocks, 256>>>(aptr, W3, tptr, N);
    gather_kernel<<<agblocks, 256>>>(b3, N);

    gemm_tc_kernel<64><<<gblocks, 256>>>(aptr, W4, tptr, N);
    gather_kernel<<<agblocks, 256>>>(b4, N);

    // pooling (+ fused output linear)
    pool_out_kernel<<<G, 64>>>(batch, Wout, bout, out_p, pooled_p, N);
}

// round 15
// speedup vs baseline: 1.6613x; 1.0303x over previous
#include <cuda_runtime.h>
#include <cuda_fp16.h>

#define MAXN 100000
#define MAXE 1600000
#define HID 64
#define SCAN_BLK 1024
#define MAX_SCAN_BLOCKS 256

// ---- scratch (device globals; no allocation allowed) ----
// g_t16 holds t'[i] = (h @ W)[i] * dis[i]  (fp16)
__device__ __align__(256) __half g_t16[MAXN * HID];
__device__ __align__(256) __half g_agg16[MAXN * HID]; // relu(conv) output (fp16)
__device__ __align__(256) float g_dis[MAXN];          // deg^{-1/2}
__device__ __align__(256) int   g_deg[MAXN];          // zero at rest (self-restoring)
__device__ __align__(256) int   g_rowptr[MAXN + 1];
__device__ __align__(256) int   g_cursor[MAXN];
__device__ __align__(256) int   g_blocksum[MAX_SCAN_BLOCKS];
__device__ __align__(256) int   g_srcs[MAXE + 4];     // CSR: src node per slot

// ---------------- prep ----------------
__global__ void count_deg_kernel(const int* __restrict__ dst, int E) {
    int e = blockIdx.x * blockDim.x + threadIdx.x;
    if (e < E) atomicAdd(&g_deg[dst[e]], 1);
}

// partial exclusive scan of g_deg; computes dis; zeroes g_deg after reading
// (keeps the at-rest state zero so count_deg needs no preceding memset).
__global__ void scan_part_kernel(int n) {
    __shared__ int sm[256];
    int tid = threadIdx.x;
    int base = blockIdx.x * SCAN_BLK + tid * 4;
    int v[4];
#pragma unroll
    for (int j = 0; j < 4; j++) {
        v[j] = (base + j < n) ? g_deg[base + j] : 0;
        if (base + j < n) {
            g_dis[base + j] = rsqrtf((float)(v[j] + 1));
            g_deg[base + j] = 0;
        }
    }
    int tsum = v[0] + v[1] + v[2] + v[3];
    sm[tid] = tsum;
    __syncthreads();
#pragma unroll
    for (int off = 1; off < 256; off <<= 1) {
        int t2 = (tid >= off) ? sm[tid - off] : 0;
        __syncthreads();
        sm[tid] += t2;
        __syncthreads();
    }
    if (tid == 255) g_blocksum[blockIdx.x] = sm[255];
    int run = sm[tid] - tsum;  // exclusive
#pragma unroll
    for (int j = 0; j < 4; j++) {
        if (base + j < n) g_rowptr[base + j] = run;
        run += v[j];
    }
}

// fused top-scan + fixup: every block redundantly prefix-sums the <=98
// block sums in smem, then applies its offsets. Also zeroes cursors.
__global__ void scan_fixup_kernel(int n, int E, int nsb) {
    __shared__ int off[128];
    int tid = threadIdx.x;
    if (tid < nsb) off[tid] = g_blocksum[tid];
    __syncthreads();
    if (tid == 0) {
        int run = 0;
        for (int i = 0; i < nsb; i++) { int t = off[i]; off[i] = run; run += t; }
    }
    __syncthreads();
    int i = blockIdx.x * blockDim.x + tid;
    if (i < n) {
        g_rowptr[i] += off[i / SCAN_BLK];
        g_cursor[i] = 0;
    } else if (i == n) {
        g_rowptr[n] = E;
    }
}

__global__ void permute_kernel(const int* __restrict__ src,
                               const int* __restrict__ dst, int E) {
    int e = blockIdx.x * blockDim.x + threadIdx.x;
    if (e < E) {
        int d = dst[e];
        int pos = atomicAdd(&g_cursor[d], 1);
        g_srcs[g_rowptr[d] + pos] = src[e];
    }
}

// ---------------- tf32 tensor-core GEMM: t16[N,64] = (in[N,K] @ W) * dis ----
__device__ __forceinline__ unsigned int f2tf32(float f) {
    unsigned int u;
    asm("cvt.rna.tf32.f32 %0, %1;" : "=r"(u) : "f"(f));
    return u;
}

__device__ __forceinline__ float ld_elem(const float* p)  { return *p; }
__device__ __forceinline__ float ld_elem(const __half* p) { return __half2float(*p); }

__device__ __forceinline__ void mma_tf32(float* c,
                                         unsigned int a0, unsigned int a1,
                                         unsigned int a2, unsigned int a3,
                                         unsigned int b0, unsigned int b1) {
    asm volatile(
        "mma.sync.aligned.m16n8k8.row.col.f32.tf32.tf32.f32 "
        "{%0,%1,%2,%3}, {%4,%5,%6,%7}, {%8,%9}, {%0,%1,%2,%3};"
        : "+f"(c[0]), "+f"(c[1]), "+f"(c[2]), "+f"(c[3])
        : "r"(a0), "r"(a1), "r"(a2), "r"(a3), "r"(b0), "r"(b1));
}

// Block: 256 threads = 8 warps; tile = 128 nodes x 64 cols; warp = 16 nodes.
// A fragments loaded directly from gmem (fp32 for layer 1, fp16 after).
// W in smem, stride 72 (== 8 mod 32: B-frag banks conflict-free).
// Epilogue: scale row r by dis[r] before fp16 store (norm factorization).
template <int K, typename T>
__global__ __launch_bounds__(256) void gemm_tc_kernel(const T* __restrict__ in,
                                                      const float* __restrict__ W,
                                                      __half* __restrict__ out, int n) {
    constexpr int SW = 72;
    __shared__ unsigned int ws[K * SW];

    const int tid = threadIdx.x;
    const int base = blockIdx.x * 128;

    {
        const float4* W4 = (const float4*)W;
        for (int i = tid; i < K * 16; i += 256) {
            int row = i >> 4, c4 = i & 15;
            float4 v = W4[i];
            uint4 u = make_uint4(f2tf32(v.x), f2tf32(v.y), f2tf32(v.z), f2tf32(v.w));
            *(uint4*)(ws + row * SW + c4 * 4) = u;
        }
    }
    __syncthreads();

    const int wid  = tid >> 5;
    const int lane = tid & 31;
    const int g    = lane >> 2;
    const int tg   = lane & 3;

    int r0 = base + wid * 16 + g;
    int r1 = r0 + 8;
    bool p0 = r0 < n, p1 = r1 < n;
    const T* x0 = in + (size_t)(p0 ? r0 : 0) * K + tg;
    const T* x1 = in + (size_t)(p1 ? r1 : 0) * K + tg;

    float c[8][4];
#pragma unroll
    for (int nt = 0; nt < 8; nt++)
#pragma unroll
        for (int j = 0; j < 4; j++) c[nt][j] = 0.f;

#pragma unroll
    for (int ks = 0; ks < K / 8; ks++) {
        unsigned int a0 = f2tf32(p0 ? ld_elem(x0 + ks * 8)     : 0.f);
        unsigned int a2 = f2tf32(p0 ? ld_elem(x0 + ks * 8 + 4) : 0.f);
        unsigned int a1 = f2tf32(p1 ? ld_elem(x1 + ks * 8)     : 0.f);
        unsigned int a3 = f2tf32(p1 ? ld_elem(x1 + ks * 8 + 4) : 0.f);
        const unsigned int* bp = ws + (ks * 8 + tg) * SW + g;
#pragma unroll
        for (int nt = 0; nt < 8; nt++) {
            unsigned int b0 = bp[nt * 8];
            unsigned int b1 = bp[nt * 8 + 4 * SW];
            mma_tf32(c[nt], a0, a1, a2, a3, b0, b1);
        }
    }

    float d0 = p0 ? g_dis[r0] : 0.f;
    float d1 = p1 ? g_dis[r1] : 0.f;
#pragma unroll
    for (int nt = 0; nt < 8; nt++) {
        int col = nt * 8 + tg * 2;
        if (p0) {
            __half2 h = __floats2half2_rn(c[nt][0] * d0, c[nt][1] * d0);
            *(__half2*)(out + (size_t)r0 * 64 + col) = h;
        }
        if (p1) {
            __half2 h = __floats2half2_rn(c[nt][2] * d1, c[nt][3] * d1);
            *(__half2*)(out + (size_t)r1 * 64 + col) = h;
        }
    }
}

// ---------------- CSR gather (warp per node, 4B edges, fp16 out) -----------
// agg[d] = relu( dis[d] * (sum_e t'[src_e] + t'[d]) + b )
__global__ __launch_bounds__(256) void gather_kernel(const float* __restrict__ b,
                                                     int n) {
    int node = blockIdx.x * 8 + (threadIdx.x >> 5);  // 8 warps/block
    int l = threadIdx.x & 31;
    if (node >= n) return;

    const __half2* t2 = (const __half2*)g_t16;

    float2 acc = __half22float2(t2[node * 32 + l]);  // self-loop term t'[d]
    int e  = g_rowptr[node];
    int e1 = g_rowptr[node + 1];
    for (; e + 4 <= e1; e += 4) {
        int s0 = g_srcs[e];
        int s1 = g_srcs[e + 1];
        int s2 = g_srcs[e + 2];
        int s3 = g_srcs[e + 3];
        float2 f0 = __half22float2(t2[s0 * 32 + l]);
        float2 f1 = __half22float2(t2[s1 * 32 + l]);
        float2 f2 = __half22float2(t2[s2 * 32 + l]);
        float2 f3 = __half22float2(t2[s3 * 32 + l]);
        acc.x += f0.x + f1.x + f2.x + f3.x;
        acc.y += f0.y + f1.y + f2.y + f3.y;
    }
    for (; e < e1; e++) {
        float2 f0 = __half22float2(t2[g_srcs[e] * 32 + l]);
        acc.x += f0.x;
        acc.y += f0.y;
    }

    float dd = g_dis[node];
    float2 bb = ((const float2*)b)[l];
    float rx = fmaxf(fmaf(dd, acc.x, bb.x), 0.f);
    float ry = fmaxf(fmaf(dd, acc.y, bb.y), 0.f);
    ((__half2*)g_agg16)[node * 32 + l] = __floats2half2_rn(rx, ry);
}

// ---------------- pooling + output linear ----------------
__global__ void pool_out_kernel(const int* __restrict__ batch,
                                const float* __restrict__ Wout,
                                const float* __restrict__ bout,
                                float* __restrict__ out,
                                float* __restrict__ pooled, int n) {
    int g = blockIdx.x;
    int c = threadIdx.x;  // 64 threads

    int a = 0, b = n;
    while (a < b) { int m = (a + b) >> 1; if (batch[m] < g) a = m + 1; else b = m; }
    int start = a;
    b = n;
    while (a < b) { int m = (a + b) >> 1; if (batch[m] <= g) a = m + 1; else b = m; }
    int end = a;

    float sum = 0.f, mx = 0.f;
#pragma unroll 4
    for (int i = start; i < end; i++) {
        float v = __half2float(g_agg16[(size_t)i * 64 + c]);  // already relu'd
        sum += v;
        mx = fmaxf(mx, v);
    }
    int cnt = end - start;
    float mean = (cnt > 0) ? sum / (float)cnt : 0.f;

    pooled[(size_t)g * 128 + c] = mean;
    pooled[(size_t)g * 128 + 64 + c] = mx;

    float partial = mean * Wout[c] + mx * Wout[64 + c];
#pragma unroll
    for (int o = 16; o > 0; o >>= 1)
        partial += __shfl_down_sync(0xffffffffu, partial, o);
    __shared__ float ws[2];
    if ((threadIdx.x & 31) == 0) ws[threadIdx.x >> 5] = partial;
    __syncthreads();
    if (threadIdx.x == 0) out[g] = ws[0] + ws[1] + bout[0];
}

// ---------------- host ----------------
extern "C" void kernel_launch(void* const* d_in, const int* in_sizes, int n_in,
                              void* d_out, int out_size) {
    const float* x     = (const float*)d_in[0];
    const int*   edge  = (const int*)d_in[1];     // int64 inputs arrive as int32
    const int*   batch = (const int*)d_in[2];
    const float* W1 = (const float*)d_in[3];  const float* b1 = (const float*)d_in[4];
    const float* W2 = (const float*)d_in[5];  const float* b2 = (const float*)d_in[6];
    const float* W3 = (const float*)d_in[7];  const float* b3 = (const float*)d_in[8];
    const float* W4 = (const float*)d_in[9];  const float* b4 = (const float*)d_in[10];
    const float* Wout = (const float*)d_in[11]; const float* bout = (const float*)d_in[12];

    int N = in_sizes[0] / 128;
    int E = in_sizes[1] / 2;
    int G = out_size / 129;  // out[G,1] + pooled[G,128]

    const int* src = edge;
    const int* dst = edge + E;

    float* out_p    = (float*)d_out;
    float* pooled_p = out_p + G;

    __half *tptr = nullptr, *aptr = nullptr;
    cudaGetSymbolAddress((void**)&tptr, g_t16);
    cudaGetSymbolAddress((void**)&aptr, g_agg16);

    int nsb      = (N + SCAN_BLK - 1) / SCAN_BLK;   // <= 98
    int gblocks  = (N + 127) / 128;
    int agblocks = (N + 7) / 8;

    // ---- prep (g_deg is zero at rest; scan_part re-zeroes it) ----
    count_deg_kernel<<<(E + 255) / 256, 256>>>(dst, E);             // 0
    scan_part_kernel<<<nsb, 256>>>(N);                              // 1  (dis + zero deg)
    scan_fixup_kernel<<<(N + 256) / 256, 256>>>(N, E, nsb);         // 2
    permute_kernel<<<(E + 255) / 256, 256>>>(src, dst, E);          // 3  (profiled slot)

    gemm_tc_kernel<128, float><<<gblocks, 256>>>(x, W1, tptr, N);   // 4
    gather_kernel<<<agblocks, 256>>>(b1, N);
    // layers 2..4 (fp16 activations in, fp16 t' out)
    gemm_tc_kernel<64, __half><<<gblocks, 256>>>(aptr, W2, tptr, N);
    gather_kernel<<<agblocks, 256>>>(b2, N);

    gemm_tc_kernel<64, __half><<<gblocks, 256>>>(aptr, W3, tptr, N);
    gather_kernel<<<agblocks, 256>>>(b3, N);

    gemm_tc_kernel<64, __half><<<gblocks, 256>>>(aptr, W4, tptr, N);
    gather_kernel<<<agblocks, 256>>>(b4, N);

    // pooling (+ fused output linear)
    pool_out_kernel<<<G, 64>>>(batch, Wout, bout, out_p, pooled_p, N);
}